// round 1
// baseline (speedup 1.0000x reference)
#include <cuda_runtime.h>
#include <cstdint>

#define BATCH 8
#define HS 256
#define WS 256
#define H 512
#define W 512
#define HW (H*W)
#define P 6                    // niter + 1
#define PH (H + 2*P)           // 524
#define PW (W + 2*P)           // 524
#define PHW (PH*PW)            // 274576
#define NITER 5

// ---------------- scratch (static device globals; no runtime allocation) ----------------
__device__ float g_dx[BATCH*HW];
__device__ float g_dy[BATCH*HW];
__device__ int   g_win[BATCH*HW];
__device__ float g_ix[2][BATCH*PHW];
__device__ float g_iy[2][BATCH*PHW];
__device__ float g_m [2][BATCH*PHW];

// ---------------- init: zero buffer-0 fields, reset winner array ----------------
__global__ void k_init() {
    int t = blockIdx.x * blockDim.x + threadIdx.x;
    if (t < BATCH*PHW) {
        g_ix[0][t] = 0.0f;
        g_iy[0][t] = 0.0f;
        g_m [0][t] = 0.0f;
    }
    if (t < BATCH*HW) {
        g_win[t] = 0x7FFFFFFF;
    }
}

// ---------------- bilinear upsample of (src - base), scale, scatter winner ----------------
__global__ void k_compute(const float* __restrict__ src, const float* __restrict__ base) {
    int t = blockIdx.x * blockDim.x + threadIdx.x;
    if (t >= BATCH*HW) return;
    int b = t / HW;
    int i = t - b*HW;
    int x = i % W;
    int y = i / W;

    // coords: c = (i+0.5)*(256/512) - 0.5 = 0.5*i - 0.25, clipped to [0, 255]
    float cy = 0.5f * (float)y - 0.25f;
    cy = fminf(fmaxf(cy, 0.0f), 255.0f);
    int ly = (int)floorf(cy);
    int hy = min(ly + 1, HS - 1);
    float wy = cy - (float)ly;

    float cx = 0.5f * (float)x - 0.25f;
    cx = fminf(fmaxf(cx, 0.0f), 255.0f);
    int lx = (int)floorf(cx);
    int hx = min(lx + 1, WS - 1);
    float wx = cx - (float)lx;

    const float* sb = src + (size_t)b * HS * WS * 2;
    int o00 = (ly*WS + lx)*2, o01 = (ly*WS + hx)*2, o10 = (hy*WS + lx)*2, o11 = (hy*WS + hx)*2;

    // channel 0 -> dx
    float d00 = sb[o00]   - base[o00];
    float d01 = sb[o01]   - base[o01];
    float d10 = sb[o10]   - base[o10];
    float d11 = sb[o11]   - base[o11];
    float r0 = d00*(1.0f-wy) + d10*wy;
    float r1 = d01*(1.0f-wy) + d11*wy;
    float dx = (r0*(1.0f-wx) + r1*wx) * (0.5f * (float)W);

    // channel 1 -> dy
    float e00 = sb[o00+1] - base[o00+1];
    float e01 = sb[o01+1] - base[o01+1];
    float e10 = sb[o10+1] - base[o10+1];
    float e11 = sb[o11+1] - base[o11+1];
    float s0 = e00*(1.0f-wy) + e10*wy;
    float s1 = e01*(1.0f-wy) + e11*wy;
    float dy = (s0*(1.0f-wx) + s1*wx) * (0.5f * (float)H);

    g_dx[t] = dx;
    g_dy[t] = dy;

    // round-half-even (matches jnp.round), oob check, winner = min source index
    float fx = rintf((float)x + dx);
    float fy = rintf((float)y + dy);
    if (fx >= 0.0f && fy >= 0.0f && fx <= (float)(W-1) && fy <= (float)(H-1)) {
        int ti = b*HW + (int)fy * W + (int)fx;
        atomicMin(&g_win[ti], i);
    }
}

// ---------------- gather winners into padded field (buffer 0) ----------------
__global__ void k_place() {
    int t = blockIdx.x * blockDim.x + threadIdx.x;
    if (t >= BATCH*HW) return;
    int w = g_win[t];
    if (w == 0x7FFFFFFF) return;
    int b = t / HW;
    int i = t - b*HW;
    int tx = i % W;
    int ty = i / W;
    int p = b*PHW + (ty + P)*PW + (tx + P);
    g_ix[0][p] = -g_dx[b*HW + w];
    g_iy[0][p] = -g_dy[b*HW + w];
    g_m [0][p] = 1.0f;
}

// ---------------- one dilation iteration: read buf s, write buf 1-s ----------------
__global__ void k_dilate(int s, const float* __restrict__ kw) {
    int t = blockIdx.x * blockDim.x + threadIdx.x;
    if (t >= BATCH*PHW) return;
    int q = t % PHW;
    int r = q / PW;
    int c = q - r*PW;

    const float* sx = g_ix[s];
    const float* sy = g_iy[s];
    const float* sm = g_m [s];

    float m  = sm[t];
    float ox = sx[t];
    float oy = sy[t];
    float om = m;

    if (m <= 0.5f) {
        bool nb = false;
        if (r > 0)     nb |= sm[t - PW] > 0.5f;
        if (r < PH-1)  nb |= sm[t + PW] > 0.5f;
        if (c > 0)     nb |= sm[t - 1]  > 0.5f;
        if (c < PW-1)  nb |= sm[t + 1]  > 0.5f;
        if (nb) {
            float ax = 0.0f, ay = 0.0f, am = 0.0f;
            #pragma unroll
            for (int ky = 0; ky < 3; ky++) {
                int rr = r + ky - 1;
                if (rr < 0 || rr >= PH) continue;
                #pragma unroll
                for (int kx = 0; kx < 3; kx++) {
                    int cc = c + kx - 1;
                    if (cc < 0 || cc >= PW) continue;
                    int u = t + (ky-1)*PW + (kx-1);
                    float k = kw[ky*3 + kx];
                    ax += k * sx[u];
                    ay += k * sy[u];
                    am += k * sm[u];
                }
            }
            ox = ax / am;
            oy = ay / am;
            om = 1.0f;
        }
    }
    g_ix[1-s][t] = ox;
    g_iy[1-s][t] = oy;
    g_m [1-s][t] = om;
}

// ---------------- one erosion iteration on mask only (OOB counts as true) ----------------
__global__ void k_erode(int s) {
    int t = blockIdx.x * blockDim.x + threadIdx.x;
    if (t >= BATCH*PHW) return;
    int q = t % PHW;
    int r = q / PW;
    int c = q - r*PW;
    const float* sm = g_m[s];
    bool m = sm[t] > 0.5f;
    if (m) {
        bool u  = (r > 0)     ? (sm[t - PW] > 0.5f) : true;
        bool d  = (r < PH-1)  ? (sm[t + PW] > 0.5f) : true;
        bool l  = (c > 0)     ? (sm[t - 1]  > 0.5f) : true;
        bool rr = (c < PW-1)  ? (sm[t + 1]  > 0.5f) : true;
        m = u && d && l && rr;
    }
    g_m[1-s][t] = m ? 1.0f : 0.0f;
}

// ---------------- compose output ----------------
// after 5 dilations (s=0,1,0,1,0) inv fields live in buffer 1;
// after 5 erosions starting from mask buf 1 (s=1,0,1,0,1) mask lives in buffer 0.
__global__ void k_final(const float* __restrict__ tgt, float* __restrict__ out) {
    int t = blockIdx.x * blockDim.x + threadIdx.x;
    if (t >= BATCH*HW) return;
    int b = t / HW;
    int i = t - b*HW;
    int x = i % W;
    int y = i / W;
    int p = b*PHW + (y + P)*PW + (x + P);
    bool m = g_m[0][p] > 0.5f;
    float vx = m ? g_ix[1][p] * (2.0f / (float)W) : 4.0f;   // 2*W * 2/W = 4
    float vy = m ? g_iy[1][p] * (2.0f / (float)H) : 4.0f;
    size_t o = ((size_t)b * HW + i) * 2;
    out[o]     = tgt[(size_t)i*2]     + vx;
    out[o + 1] = tgt[(size_t)i*2 + 1] + vy;
}

extern "C" void kernel_launch(void* const* d_in, const int* in_sizes, int n_in,
                              void* d_out, int out_size) {
    // identify inputs by unique element counts (robust to ordering)
    const float* src  = nullptr;   // 8*256*256*2  = 1048576
    const float* kw   = nullptr;   // 3*3          = 9
    const float* base = nullptr;   // 1*256*256*2  = 131072
    const float* tgt  = nullptr;   // 1*512*512*2  = 524288
    for (int j = 0; j < n_in; j++) {
        switch (in_sizes[j]) {
            case 1048576: src  = (const float*)d_in[j]; break;
            case 9:       kw   = (const float*)d_in[j]; break;
            case 131072:  base = (const float*)d_in[j]; break;
            case 524288:  tgt  = (const float*)d_in[j]; break;
            default: break; // niter (size 1) ignored; fixed at 5
        }
    }
    float* out = (float*)d_out;

    const int TB = 256;
    const int nbig   = (BATCH*PHW + TB - 1) / TB;   // covers padded domain (also >= BATCH*HW count? no)
    const int nsmall = (BATCH*HW  + TB - 1) / TB;

    k_init<<<nbig, TB>>>();
    k_compute<<<nsmall, TB>>>(src, base);
    k_place<<<nsmall, TB>>>();

    // 5 dilation iterations: 0->1->0->1->0->1 (final in buffer 1)
    int s = 0;
    for (int it = 0; it < NITER; it++) {
        k_dilate<<<nbig, TB>>>(s, kw);
        s = 1 - s;
    }
    // 5 erosion iterations on mask starting from buffer 1 (final in buffer 0)
    for (int it = 0; it < NITER; it++) {
        k_erode<<<nbig, TB>>>(s);
        s = 1 - s;
    }

    k_final<<<nsmall, TB>>>(tgt, out);
}

// round 2
// speedup vs baseline: 1.1597x; 1.1597x over previous
#include <cuda_runtime.h>
#include <cstdint>

#define BATCH 8
#define HS 256
#define WS 256
#define H 512
#define W 512
#define HW (H*W)
#define NITER 5

#define TILE 32
#define HALO 10                 // 2*NITER
#define S (TILE + 2*HALO)       // 52
#define SS (S*S)                // 2704
#define NC ((SS + 255) / 256)   // 11 cells per thread

// ---------------- scratch (static device globals; no runtime allocation) ----------------
__device__ float g_dx  [BATCH*HW];
__device__ float g_dy  [BATCH*HW];
__device__ int   g_win [BATCH*HW];
__device__ float g_ivx [BATCH*HW];
__device__ float g_ivy [BATCH*HW];
__device__ float g_mask[BATCH*HW];

// ---------------- reset winner array ----------------
__global__ void k_init() {
    int t = blockIdx.x * blockDim.x + threadIdx.x;
    if (t < BATCH*HW) g_win[t] = 0x7FFFFFFF;
}

// ---------------- bilinear upsample of (src - base), scale, scatter winner ----------------
__global__ void k_compute(const float* __restrict__ src, const float* __restrict__ base) {
    int t = blockIdx.x * blockDim.x + threadIdx.x;
    if (t >= BATCH*HW) return;
    int b = t / HW;
    int i = t - b*HW;
    int x = i % W;
    int y = i / W;

    // coords: c = (i+0.5)*(256/512) - 0.5 = 0.5*i - 0.25, clipped to [0, 255]
    float cy = 0.5f * (float)y - 0.25f;
    cy = fminf(fmaxf(cy, 0.0f), 255.0f);
    int ly = (int)floorf(cy);
    int hy = min(ly + 1, HS - 1);
    float wy = cy - (float)ly;

    float cx = 0.5f * (float)x - 0.25f;
    cx = fminf(fmaxf(cx, 0.0f), 255.0f);
    int lx = (int)floorf(cx);
    int hx = min(lx + 1, WS - 1);
    float wx = cx - (float)lx;

    const float* sb = src + (size_t)b * HS * WS * 2;
    int o00 = (ly*WS + lx)*2, o01 = (ly*WS + hx)*2, o10 = (hy*WS + lx)*2, o11 = (hy*WS + hx)*2;

    float d00 = sb[o00]   - base[o00];
    float d01 = sb[o01]   - base[o01];
    float d10 = sb[o10]   - base[o10];
    float d11 = sb[o11]   - base[o11];
    float r0 = d00*(1.0f-wy) + d10*wy;
    float r1 = d01*(1.0f-wy) + d11*wy;
    float dx = (r0*(1.0f-wx) + r1*wx) * (0.5f * (float)W);

    float e00 = sb[o00+1] - base[o00+1];
    float e01 = sb[o01+1] - base[o01+1];
    float e10 = sb[o10+1] - base[o10+1];
    float e11 = sb[o11+1] - base[o11+1];
    float s0 = e00*(1.0f-wy) + e10*wy;
    float s1 = e01*(1.0f-wy) + e11*wy;
    float dy = (s0*(1.0f-wx) + s1*wx) * (0.5f * (float)H);

    g_dx[t] = dx;
    g_dy[t] = dy;

    // round-half-even (matches jnp.round), oob check, winner = min source index
    float fx = rintf((float)x + dx);
    float fy = rintf((float)y + dy);
    if (fx >= 0.0f && fy >= 0.0f && fx <= (float)(W-1) && fy <= (float)(H-1)) {
        int ti = b*HW + (int)fy * W + (int)fx;
        atomicMin(&g_win[ti], i);
    }
}

// ---------------- gather winners -> dense unpadded fields (mask, -dx, -dy) ----------------
__global__ void k_place() {
    int t = blockIdx.x * blockDim.x + threadIdx.x;
    if (t >= BATCH*HW) return;
    int w = g_win[t];
    int b = t / HW;
    float vx = 0.0f, vy = 0.0f, m = 0.0f;
    if (w != 0x7FFFFFFF) {
        vx = -g_dx[b*HW + w];
        vy = -g_dy[b*HW + w];
        m  = 1.0f;
    }
    g_ivx [t] = vx;
    g_ivy [t] = vy;
    g_mask[t] = m;
}

// ---------------- fused: 5x dilation + 5x erosion + compose, all in shared memory ----------
__global__ __launch_bounds__(256) void k_fused(const float* __restrict__ kw,
                                               const float* __restrict__ tgt,
                                               float* __restrict__ out) {
    __shared__ float smM[SS];
    __shared__ float smX[SS];
    __shared__ float smY[SS];
    __shared__ float skw[9];

    int b   = blockIdx.z;
    int tx0 = blockIdx.x * TILE - HALO;
    int ty0 = blockIdx.y * TILE - HALO;
    int tid = threadIdx.x;

    if (tid < 9) skw[tid] = kw[tid];

    const float* gm = g_mask + (size_t)b * HW;
    const float* gx = g_ivx  + (size_t)b * HW;
    const float* gy = g_ivy  + (size_t)b * HW;

    // load 52x52 tile with zero extension beyond the 512x512 domain
    #pragma unroll
    for (int j = 0; j < NC; j++) {
        int idx = tid + j*256;
        if (idx < SS) {
            int r = idx / S, c = idx - r*S;
            int py = ty0 + r, px = tx0 + c;
            float m = 0.0f, vx = 0.0f, vy = 0.0f;
            if (px >= 0 && px < W && py >= 0 && py < H) {
                int g = py*W + px;
                m  = gm[g];
                vx = gx[g];
                vy = gy[g];
            }
            smM[idx] = m; smX[idx] = vx; smY[idx] = vy;
        }
    }
    __syncthreads();

    // ---- 5 dilation iterations (register-staged; all reads precede all writes) ----
    for (int it = 0; it < NITER; it++) {
        float nm[NC], nx[NC], ny[NC];
        #pragma unroll
        for (int j = 0; j < NC; j++) {
            int idx = tid + j*256;
            if (idx < SS) {
                int r = idx / S, c = idx - r*S;
                float m  = smM[idx];
                float ox = smX[idx];
                float oy = smY[idx];
                float om = m;
                if (r >= 1 && r < S-1 && c >= 1 && c < S-1 && m <= 0.5f) {
                    bool nb = (smM[idx-S] > 0.5f) | (smM[idx+S] > 0.5f) |
                              (smM[idx-1] > 0.5f) | (smM[idx+1] > 0.5f);
                    if (nb) {
                        float am = 0.0f, ax = 0.0f, ay = 0.0f;
                        #pragma unroll
                        for (int ky = 0; ky < 3; ky++) {
                            #pragma unroll
                            for (int kx = 0; kx < 3; kx++) {
                                int u = idx + (ky-1)*S + (kx-1);
                                float k = skw[ky*3 + kx];
                                am += k * smM[u];
                                ax += k * smX[u];
                                ay += k * smY[u];
                            }
                        }
                        ox = ax / am;
                        oy = ay / am;
                        om = 1.0f;
                    }
                }
                nm[j] = om; nx[j] = ox; ny[j] = oy;
            }
        }
        __syncthreads();
        #pragma unroll
        for (int j = 0; j < NC; j++) {
            int idx = tid + j*256;
            if (idx < SS) { smM[idx] = nm[j]; smX[idx] = nx[j]; smY[idx] = ny[j]; }
        }
        __syncthreads();
    }

    // ---- 5 erosion iterations on the mask only ----
    for (int it = 0; it < NITER; it++) {
        float nm[NC];
        #pragma unroll
        for (int j = 0; j < NC; j++) {
            int idx = tid + j*256;
            if (idx < SS) {
                int r = idx / S, c = idx - r*S;
                float m = smM[idx];
                if (r >= 1 && r < S-1 && c >= 1 && c < S-1 && m > 0.5f) {
                    bool keep = (smM[idx-S] > 0.5f) & (smM[idx+S] > 0.5f) &
                                (smM[idx-1] > 0.5f) & (smM[idx+1] > 0.5f);
                    m = keep ? 1.0f : 0.0f;
                }
                nm[j] = m;
            }
        }
        __syncthreads();
        #pragma unroll
        for (int j = 0; j < NC; j++) {
            int idx = tid + j*256;
            if (idx < SS) smM[idx] = nm[j];
        }
        __syncthreads();
    }

    // ---- compose interior 32x32 and write output ----
    #pragma unroll
    for (int j = 0; j < NC; j++) {
        int idx = tid + j*256;
        if (idx < SS) {
            int r = idx / S, c = idx - r*S;
            if (r >= HALO && r < S-HALO && c >= HALO && c < S-HALO) {
                int py = ty0 + r, px = tx0 + c;  // guaranteed in [0, 512)
                int g = py*W + px;
                bool m = smM[idx] > 0.5f;
                float vx = m ? smX[idx] * (2.0f / (float)W) : 4.0f;  // 2*W * (2/W) = 4
                float vy = m ? smY[idx] * (2.0f / (float)H) : 4.0f;
                size_t o = ((size_t)b * HW + g) * 2;
                out[o]     = tgt[(size_t)g*2]     + vx;
                out[o + 1] = tgt[(size_t)g*2 + 1] + vy;
            }
        }
    }
}

extern "C" void kernel_launch(void* const* d_in, const int* in_sizes, int n_in,
                              void* d_out, int out_size) {
    // identify inputs by unique element counts (robust to ordering)
    const float* src  = nullptr;   // 8*256*256*2  = 1048576
    const float* kw   = nullptr;   // 3*3          = 9
    const float* base = nullptr;   // 1*256*256*2  = 131072
    const float* tgt  = nullptr;   // 1*512*512*2  = 524288
    for (int j = 0; j < n_in; j++) {
        switch (in_sizes[j]) {
            case 1048576: src  = (const float*)d_in[j]; break;
            case 9:       kw   = (const float*)d_in[j]; break;
            case 131072:  base = (const float*)d_in[j]; break;
            case 524288:  tgt  = (const float*)d_in[j]; break;
            default: break; // niter (size 1) ignored; fixed at 5
        }
    }
    float* out = (float*)d_out;

    const int TB = 256;
    const int n  = (BATCH*HW + TB - 1) / TB;

    k_init   <<<n, TB>>>();
    k_compute<<<n, TB>>>(src, base);
    k_place  <<<n, TB>>>();

    dim3 grid(W/TILE, H/TILE, BATCH);   // 16 x 16 x 8
    k_fused<<<grid, TB>>>(kw, tgt, out);
}